// round 5
// baseline (speedup 1.0000x reference)
#include <cuda_runtime.h>
#include <cuda_bf16.h>
#include <cstdint>

#define NN   10368
#define CC   512
#define HS   128
#define SPL  81
#define KSP  128         // NN / SPL

// ---------------- device scratch ----------------
__device__ __nv_bfloat16 g_Wcat[256 * CC];
__device__ __nv_bfloat16 g_xb[CC * NN];
__device__ __nv_bfloat16 g_xbT[NN * CC];
__device__ __nv_bfloat16 g_fiT[NN * HS];
__device__ __nv_bfloat16 g_fj[HS * NN];
__device__ float         g_Tpart[SPL * HS * CC];
__device__ __nv_bfloat16 g_Tt[CC * HS];

// ---------------- helpers ----------------
__device__ __forceinline__ uint32_t smem_u32(const void* p) {
    uint32_t a;
    asm("{ .reg .u64 t; cvta.to.shared.u64 t, %1; cvt.u32.u64 %0, t; }" : "=r"(a) : "l"(p));
    return a;
}
__device__ __forceinline__ void ldsm4(uint32_t addr, uint32_t& r0, uint32_t& r1,
                                      uint32_t& r2, uint32_t& r3) {
    asm volatile("ldmatrix.sync.aligned.m8n8.x4.shared.b16 {%0,%1,%2,%3}, [%4];"
                 : "=r"(r0), "=r"(r1), "=r"(r2), "=r"(r3) : "r"(addr));
}
__device__ __forceinline__ void mma_bf16(float* c, uint32_t a0, uint32_t a1, uint32_t a2,
                                         uint32_t a3, uint32_t b0, uint32_t b1) {
    asm volatile("mma.sync.aligned.m16n8k16.row.col.f32.bf16.bf16.f32 "
                 "{%0,%1,%2,%3}, {%4,%5,%6,%7}, {%8,%9}, {%0,%1,%2,%3};"
                 : "+f"(c[0]), "+f"(c[1]), "+f"(c[2]), "+f"(c[3])
                 : "r"(a0), "r"(a1), "r"(a2), "r"(a3), "r"(b0), "r"(b1));
}
#define CP16(dst, src)  asm volatile("cp.async.cg.shared.global [%0], [%1], 16;" :: "r"(dst), "l"(src))
#define CP_COMMIT()     asm volatile("cp.async.commit_group;" ::: "memory")
#define CP_WAIT0()      asm volatile("cp.async.wait_group 0;" ::: "memory")

#define SM_STRIDE 72                       // bf16/row (64 + 8 pad)
#define STAGE_A   (128 * SM_STRIDE * 2)    // 18432 B
#define STAGE_B   (64 * SM_STRIDE * 2)     // 9216 B
#define STAGE_SZ  (STAGE_A + STAGE_B)      // 27648 B
#define SMEM_TOT  (2 * STAGE_SZ)           // 55296 B

// GEMM core: CTA 128m x 64n, 8 warps (2m x 4n), warp 64m x 16n, BK=64,
// K-major operands, 2-stage cp.async double buffer.  acc[4][2][4]
__device__ __forceinline__ void gemm_pipe(const __nv_bfloat16* __restrict__ Ag, size_t lda,
                                          const __nv_bfloat16* __restrict__ Bg, size_t ldb,
                                          int K, float acc[4][2][4], char* sm) {
    const int tid = threadIdx.x, lane = tid & 31, wid = tid >> 5;
    const int mBase = (wid >> 2) * 64, nBase = (wid & 3) * 16;
    const uint32_t sbase = smem_u32(sm);

    const int a_r = lane & 15, a_k = (lane >> 4) * 8;
    const int b_r = ((lane >> 4) << 3) + (lane & 7), b_k = ((lane >> 3) & 1) * 8;
    const uint32_t aOff = (uint32_t)((mBase + a_r) * SM_STRIDE + a_k) * 2;
    const uint32_t bOff = (uint32_t)(STAGE_A + ((nBase + b_r) * SM_STRIDE + b_k) * 2);

    const int nstages = K / 64;
    auto load_stage = [&](int s, int k0) {
        const uint32_t st = sbase + s * STAGE_SZ;
#pragma unroll
        for (int i = tid; i < 1536; i += 256) {   // 1024 A vec4 + 512 B vec4
            const int which = (i >= 1024);
            const int idx = which ? (i - 1024) : i;
            const int row = idx >> 3, q = (idx & 7) * 8;
            const uint32_t dst = st + which * STAGE_A + (uint32_t)(row * SM_STRIDE + q) * 2;
            const __nv_bfloat16* src = which ? (Bg + (size_t)row * ldb + k0 + q)
                                             : (Ag + (size_t)row * lda + k0 + q);
            CP16(dst, src);
        }
    };

    load_stage(0, 0);
    CP_COMMIT();
    int cur = 0;
    for (int s = 1; s <= nstages; s++) {
        CP_WAIT0();
        __syncthreads();
        if (s < nstages) { load_stage(cur ^ 1, s * 64); CP_COMMIT(); }
        const uint32_t stA = sbase + cur * STAGE_SZ + aOff;
        const uint32_t stB = sbase + cur * STAGE_SZ + bOff;
#pragma unroll
        for (int kk = 0; kk < 4; kk++) {
            uint32_t af[4][4], bf[4];
#pragma unroll
            for (int mf = 0; mf < 4; mf++)
                ldsm4(stA + (uint32_t)(mf * 16 * SM_STRIDE + kk * 16) * 2,
                      af[mf][0], af[mf][1], af[mf][2], af[mf][3]);
            ldsm4(stB + (uint32_t)(kk * 16) * 2, bf[0], bf[1], bf[2], bf[3]);
#pragma unroll
            for (int mf = 0; mf < 4; mf++) {
                mma_bf16(acc[mf][0], af[mf][0], af[mf][1], af[mf][2], af[mf][3], bf[0], bf[1]);
                mma_bf16(acc[mf][1], af[mf][0], af[mf][1], af[mf][2], af[mf][3], bf[2], bf[3]);
            }
        }
        __syncthreads();
        cur ^= 1;
    }
}

// ---------------- k0: weights -> bf16 concat ----------------
__global__ void k0_w(const float* __restrict__ Wi, const float* __restrict__ Wj) {
    int i = blockIdx.x * 256 + threadIdx.x;
    if (i < 256 * CC)
        g_Wcat[i] = __float2bfloat16(i < HS * CC ? Wi[i] : Wj[i - HS * CC]);
}

// ---------------- prepass: x -> bf16 + bf16 transpose ----------------
__global__ void k_pre(const float* __restrict__ x) {
    __shared__ float t[32][33];
    const int n0 = blockIdx.x * 32, c0 = blockIdx.y * 32;
    const int tx = threadIdx.x, ty = threadIdx.y;
#pragma unroll
    for (int i = 0; i < 4; i++) {
        int r = ty + i * 8;
        float v = x[(size_t)(c0 + r) * NN + n0 + tx];
        t[r][tx] = v;
        g_xb[(size_t)(c0 + r) * NN + n0 + tx] = __float2bfloat16(v);
    }
    __syncthreads();
#pragma unroll
    for (int i = 0; i < 4; i++) {
        int r = ty + i * 8;
        g_xbT[(size_t)(n0 + r) * CC + c0 + tx] = __float2bfloat16(t[tx][r]);
    }
}

// ---------------- k1: f = Wcat @ x  (M=256, N=NN, K=512). grid (162, 2) ----------------
__global__ __launch_bounds__(256) void k1(const float* __restrict__ bi,
                                          const float* __restrict__ bj) {
    extern __shared__ __align__(16) char sm[];
    const int n0 = blockIdx.x * 64, m0 = blockIdx.y * 128;
    float acc[4][2][4] = {};
    gemm_pipe(g_Wcat + (size_t)m0 * CC, CC, g_xbT + (size_t)n0 * CC, CC, CC, acc, sm);

    const int tid = threadIdx.x, lane = tid & 31, wid = tid >> 5;
    const int mBase = (wid >> 2) * 64, nBase = (wid & 3) * 16;
    const int r = lane >> 2, cc = (lane & 3) * 2;
    const float* bsrc = (m0 == 0) ? bi : bj;
#pragma unroll
    for (int mf = 0; mf < 4; mf++)
#pragma unroll
        for (int e = 0; e < 2; e++) {
            const int m = mBase + mf * 16 + r + e * 8;
            const float bias = bsrc[m];
#pragma unroll
            for (int nf = 0; nf < 2; nf++) {
                const int n = n0 + nBase + nf * 8 + cc;
                const float v0 = acc[mf][nf][e * 2] + bias;
                const float v1 = acc[mf][nf][e * 2 + 1] + bias;
                if (m0 == 0) {
                    g_fiT[(size_t)n * HS + m]       = __float2bfloat16(v0);
                    g_fiT[(size_t)(n + 1) * HS + m] = __float2bfloat16(v1);
                } else {
                    *(__nv_bfloat162*)(g_fj + (size_t)m * NN + n) =
                        __floats2bfloat162_rn(v0, v1);
                }
            }
        }
}

// ---------------- k2: Tpart[s] = fj @ xb^T per chunk. grid (8, SPL) ----------------
__global__ __launch_bounds__(256) void k2() {
    extern __shared__ __align__(16) char sm[];
    const int c0 = blockIdx.x * 64, sp = blockIdx.y;
    const size_t koff = (size_t)sp * KSP;
    float acc[4][2][4] = {};
    gemm_pipe(g_fj + koff, NN, g_xb + (size_t)c0 * NN + koff, NN, KSP, acc, sm);

    const int tid = threadIdx.x, lane = tid & 31, wid = tid >> 5;
    const int mBase = (wid >> 2) * 64, nBase = (wid & 3) * 16;
    const int r = lane >> 2, cc = (lane & 3) * 2;
    float* dst = g_Tpart + (size_t)sp * HS * CC;
#pragma unroll
    for (int mf = 0; mf < 4; mf++)
#pragma unroll
        for (int e = 0; e < 2; e++) {
            const int h = mBase + mf * 16 + r + e * 8;
#pragma unroll
            for (int nf = 0; nf < 2; nf++) {
                const int c = c0 + nBase + nf * 8 + cc;
                *(float2*)(dst + (size_t)h * CC + c) =
                    make_float2(acc[mf][nf][e * 2], acc[mf][nf][e * 2 + 1]);
            }
        }
}

// ---------------- reduce: Tt[c][h] = bf16(sum_s Tpart), float4 ----------------
__global__ void kred() {
    int i4 = blockIdx.x * 256 + threadIdx.x;    // over 16384 float4s
    if (i4 < HS * CC / 4) {
        float4 s = make_float4(0.f, 0.f, 0.f, 0.f);
        const float4* src = (const float4*)g_Tpart;
        for (int p = 0; p < SPL; p++) {
            float4 v = src[(size_t)p * (HS * CC / 4) + i4];
            s.x += v.x; s.y += v.y; s.z += v.z; s.w += v.w;
        }
        int i = i4 * 4;
        int h = i >> 9, c = i & 511;           // 4 consecutive c, same h
        g_Tt[(size_t)(c + 0) * HS + h] = __float2bfloat16(s.x);
        g_Tt[(size_t)(c + 1) * HS + h] = __float2bfloat16(s.y);
        g_Tt[(size_t)(c + 2) * HS + h] = __float2bfloat16(s.z);
        g_Tt[(size_t)(c + 3) * HS + h] = __float2bfloat16(s.w);
    }
}

// ---------------- k4: out = x + scale * (fiT @ Tt^T)^T. grid (81, 8) ----------------
#define EPS 132   // epilogue smem stride (floats), 528B (16B-aligned, conflict-free)
__global__ __launch_bounds__(256) void k4(const float* __restrict__ x,
                                          const float* __restrict__ agg,
                                          float* __restrict__ out) {
    extern __shared__ __align__(16) char sm[];
    const int n0 = blockIdx.x * 128, c0 = blockIdx.y * 64;
    float acc[4][2][4] = {};
    gemm_pipe(g_fiT + (size_t)n0 * HS, HS, g_Tt + (size_t)c0 * HS, HS, HS, acc, sm);

    const int tid = threadIdx.x, lane = tid & 31, wid = tid >> 5;
    const int mBase = (wid >> 2) * 64, nBase = (wid & 3) * 16;
    const int r = lane >> 2, cc = (lane & 3) * 2;

    // stage [64 c][128 n] fp32 tile in smem (conflict-free: stride 132)
    float* smf = (float*)sm;
    __syncthreads();
#pragma unroll
    for (int mf = 0; mf < 4; mf++)
#pragma unroll
        for (int e = 0; e < 2; e++) {
            const int nl = mBase + mf * 16 + r + e * 8;
#pragma unroll
            for (int nf = 0; nf < 2; nf++) {
                const int cl = nBase + nf * 8 + cc;
                smf[(cl + 0) * EPS + nl] = acc[mf][nf][e * 2];
                smf[(cl + 1) * EPS + nl] = acc[mf][nf][e * 2 + 1];
            }
        }
    __syncthreads();

    const float scale = agg[0] * (1.0f / (float)NN);
#pragma unroll
    for (int t = tid; t < 2048; t += 256) {      // 64 rows x 32 float4
        const int row = t >> 5, col = (t & 31) * 4;
        float4 v = *(float4*)(smf + row * EPS + col);
        const size_t gi = (size_t)(c0 + row) * NN + n0 + col;
        float4 xv = *(const float4*)(x + gi);
        v.x = xv.x + scale * v.x;  v.y = xv.y + scale * v.y;
        v.z = xv.z + scale * v.z;  v.w = xv.w + scale * v.w;
        *(float4*)(out + gi) = v;
    }
}

// ---------------- launch ----------------
extern "C" void kernel_launch(void* const* d_in, const int* in_sizes, int n_in,
                              void* d_out, int out_size) {
    const float* features = (const float*)d_in[0];
    const float* Wi       = (const float*)d_in[1];
    const float* bi       = (const float*)d_in[2];
    const float* Wj       = (const float*)d_in[3];
    const float* bj       = (const float*)d_in[4];
    const float* agg      = (const float*)d_in[5];
    float* out = (float*)d_out;

    cudaFuncSetAttribute(k1, cudaFuncAttributeMaxDynamicSharedMemorySize, SMEM_TOT);
    cudaFuncSetAttribute(k2, cudaFuncAttributeMaxDynamicSharedMemorySize, SMEM_TOT);
    cudaFuncSetAttribute(k4, cudaFuncAttributeMaxDynamicSharedMemorySize, SMEM_TOT);

    k0_w<<<512, 256>>>(Wi, Wj);
    k_pre<<<dim3(NN / 32, CC / 32), dim3(32, 8)>>>(features);
    k1<<<dim3(162, 2), 256, SMEM_TOT>>>(bi, bj);
    k2<<<dim3(8, SPL), 256, SMEM_TOT>>>();
    kred<<<64, 256>>>();
    k4<<<dim3(81, 8), 256, SMEM_TOT>>>(features, agg, out);
}

// round 9
// speedup vs baseline: 1.0093x; 1.0093x over previous
#include <cuda_runtime.h>
#include <cuda_bf16.h>
#include <cstdint>

#define NN   10368
#define CC   512
#define HS   128
#define SPL  81
#define KSP  128         // NN / SPL

// ---------------- device scratch ----------------
__device__ __nv_bfloat16 g_Wcat[256 * CC];
__device__ __nv_bfloat16 g_xb[CC * NN];
__device__ __nv_bfloat16 g_xbT[NN * CC];
__device__ __nv_bfloat16 g_fiT[NN * HS];
__device__ __nv_bfloat16 g_fj[HS * NN];
__device__ float         g_Tpart[SPL * HS * CC];
__device__ __nv_bfloat16 g_Tt[CC * HS];

// ---------------- helpers ----------------
__device__ __forceinline__ uint32_t smem_u32(const void* p) {
    uint32_t a;
    asm("{ .reg .u64 t; cvta.to.shared.u64 t, %1; cvt.u32.u64 %0, t; }" : "=r"(a) : "l"(p));
    return a;
}
__device__ __forceinline__ void ldsm4(uint32_t addr, uint32_t& r0, uint32_t& r1,
                                      uint32_t& r2, uint32_t& r3) {
    asm volatile("ldmatrix.sync.aligned.m8n8.x4.shared.b16 {%0,%1,%2,%3}, [%4];"
                 : "=r"(r0), "=r"(r1), "=r"(r2), "=r"(r3) : "r"(addr));
}
__device__ __forceinline__ void mma_bf16(float* c, uint32_t a0, uint32_t a1, uint32_t a2,
                                         uint32_t a3, uint32_t b0, uint32_t b1) {
    asm volatile("mma.sync.aligned.m16n8k16.row.col.f32.bf16.bf16.f32 "
                 "{%0,%1,%2,%3}, {%4,%5,%6,%7}, {%8,%9}, {%0,%1,%2,%3};"
                 : "+f"(c[0]), "+f"(c[1]), "+f"(c[2]), "+f"(c[3])
                 : "r"(a0), "r"(a1), "r"(a2), "r"(a3), "r"(b0), "r"(b1));
}
#define CP16(dst, src)  asm volatile("cp.async.cg.shared.global [%0], [%1], 16;" :: "r"(dst), "l"(src))
#define CP_COMMIT()     asm volatile("cp.async.commit_group;" ::: "memory")
#define CP_WAIT0()      asm volatile("cp.async.wait_group 0;" ::: "memory")

#define SM_STRIDE 72                       // bf16/row (64 + 8 pad)
#define STAGE_A   (128 * SM_STRIDE * 2)    // 18432 B
#define STAGE_B   (64 * SM_STRIDE * 2)     // 9216 B
#define STAGE_SZ  (STAGE_A + STAGE_B)      // 27648 B
#define SMEM_TOT  (2 * STAGE_SZ)           // 55296 B

// GEMM core: CTA 128m x 64n, 8 warps (2m x 4n), warp 64m x 16n, BK=64,
// K-major operands, 2-stage cp.async double buffer.  acc[4][2][4]
__device__ __forceinline__ void gemm_pipe(const __nv_bfloat16* __restrict__ Ag, size_t lda,
                                          const __nv_bfloat16* __restrict__ Bg, size_t ldb,
                                          int K, float acc[4][2][4], char* sm) {
    const int tid = threadIdx.x, lane = tid & 31, wid = tid >> 5;
    const int mBase = (wid >> 2) * 64, nBase = (wid & 3) * 16;
    const uint32_t sbase = smem_u32(sm);

    const int a_r = lane & 15, a_k = (lane >> 4) * 8;
    const int b_r = ((lane >> 4) << 3) + (lane & 7), b_k = ((lane >> 3) & 1) * 8;
    const uint32_t aOff = (uint32_t)((mBase + a_r) * SM_STRIDE + a_k) * 2;
    const uint32_t bOff = (uint32_t)(STAGE_A + ((nBase + b_r) * SM_STRIDE + b_k) * 2);

    const int nstages = K / 64;
    auto load_stage = [&](int s, int k0) {
        const uint32_t st = sbase + s * STAGE_SZ;
#pragma unroll
        for (int i = tid; i < 1536; i += 256) {
            const int which = (i >= 1024);
            const int idx = which ? (i - 1024) : i;
            const int row = idx >> 3, q = (idx & 7) * 8;
            const uint32_t dst = st + which * STAGE_A + (uint32_t)(row * SM_STRIDE + q) * 2;
            const __nv_bfloat16* src = which ? (Bg + (size_t)row * ldb + k0 + q)
                                             : (Ag + (size_t)row * lda + k0 + q);
            CP16(dst, src);
        }
    };

    load_stage(0, 0);
    CP_COMMIT();
    int cur = 0;
    for (int s = 1; s <= nstages; s++) {
        CP_WAIT0();
        __syncthreads();
        if (s < nstages) { load_stage(cur ^ 1, s * 64); CP_COMMIT(); }
        const uint32_t stA = sbase + cur * STAGE_SZ + aOff;
        const uint32_t stB = sbase + cur * STAGE_SZ + bOff;
#pragma unroll
        for (int kk = 0; kk < 4; kk++) {
            uint32_t af[4][4], bf[4];
#pragma unroll
            for (int mf = 0; mf < 4; mf++)
                ldsm4(stA + (uint32_t)(mf * 16 * SM_STRIDE + kk * 16) * 2,
                      af[mf][0], af[mf][1], af[mf][2], af[mf][3]);
            ldsm4(stB + (uint32_t)(kk * 16) * 2, bf[0], bf[1], bf[2], bf[3]);
#pragma unroll
            for (int mf = 0; mf < 4; mf++) {
                mma_bf16(acc[mf][0], af[mf][0], af[mf][1], af[mf][2], af[mf][3], bf[0], bf[1]);
                mma_bf16(acc[mf][1], af[mf][0], af[mf][1], af[mf][2], af[mf][3], bf[2], bf[3]);
            }
        }
        __syncthreads();
        cur ^= 1;
    }
}

// ---------------- k0: weights -> bf16 concat ----------------
__global__ void k0_w(const float* __restrict__ Wi, const float* __restrict__ Wj) {
    int i = blockIdx.x * 256 + threadIdx.x;
    if (i < 256 * CC)
        g_Wcat[i] = __float2bfloat16(i < HS * CC ? Wi[i] : Wj[i - HS * CC]);
}

// ---------------- prepass: x -> bf16 + bf16 transpose ----------------
__global__ void k_pre(const float* __restrict__ x) {
    __shared__ float t[32][33];
    const int n0 = blockIdx.x * 32, c0 = blockIdx.y * 32;
    const int tx = threadIdx.x, ty = threadIdx.y;
#pragma unroll
    for (int i = 0; i < 4; i++) {
        int r = ty + i * 8;
        float v = x[(size_t)(c0 + r) * NN + n0 + tx];
        t[r][tx] = v;
        g_xb[(size_t)(c0 + r) * NN + n0 + tx] = __float2bfloat16(v);
    }
    __syncthreads();
#pragma unroll
    for (int i = 0; i < 4; i++) {
        int r = ty + i * 8;
        g_xbT[(size_t)(n0 + r) * CC + c0 + tx] = __float2bfloat16(t[tx][r]);
    }
}

// ---------------- k1: f = Wcat @ x  (M=256, N=NN, K=512). grid (162, 2) ----------------
#define FIS 136   // fi staging stride (bf16)
#define FJS 72    // fj staging stride (bf16)
__global__ __launch_bounds__(256) void k1(const float* __restrict__ bi,
                                          const float* __restrict__ bj) {
    extern __shared__ __align__(16) char sm[];
    const int n0 = blockIdx.x * 64, m0 = blockIdx.y * 128;
    float acc[4][2][4] = {};
    gemm_pipe(g_Wcat + (size_t)m0 * CC, CC, g_xbT + (size_t)n0 * CC, CC, CC, acc, sm);

    const int tid = threadIdx.x, lane = tid & 31, wid = tid >> 5;
    const int mBase = (wid >> 2) * 64, nBase = (wid & 3) * 16;
    const int r = lane >> 2, cc = (lane & 3) * 2;
    const float* bsrc = (m0 == 0) ? bi : bj;
    __nv_bfloat16* smb = (__nv_bfloat16*)sm;

    if (m0 == 0) {
        // stage fi transposed: S[64 n][128 h], then coalesced fiT row writes
#pragma unroll
        for (int mf = 0; mf < 4; mf++)
#pragma unroll
            for (int e = 0; e < 2; e++) {
                const int m = mBase + mf * 16 + r + e * 8;
                const float bias = bsrc[m];
#pragma unroll
                for (int nf = 0; nf < 2; nf++) {
                    const int nl = nBase + nf * 8 + cc;
                    smb[(nl + 0) * FIS + m] = __float2bfloat16(acc[mf][nf][e * 2] + bias);
                    smb[(nl + 1) * FIS + m] = __float2bfloat16(acc[mf][nf][e * 2 + 1] + bias);
                }
            }
        __syncthreads();
#pragma unroll
        for (int t = tid; t < 64 * 16; t += 256) {        // 64 rows x 16 uint4
            const int row = t >> 4, q = (t & 15) * 8;
            *(uint4*)(g_fiT + (size_t)(n0 + row) * HS + q) = *(uint4*)(smb + row * FIS + q);
        }
    } else {
        // stage fj row-major: S[128 m][64 n], then coalesced row writes
#pragma unroll
        for (int mf = 0; mf < 4; mf++)
#pragma unroll
            for (int e = 0; e < 2; e++) {
                const int m = mBase + mf * 16 + r + e * 8;
                const float bias = bsrc[m];
#pragma unroll
                for (int nf = 0; nf < 2; nf++) {
                    const int nl = nBase + nf * 8 + cc;
                    *(__nv_bfloat162*)(smb + m * FJS + nl) =
                        __floats2bfloat162_rn(acc[mf][nf][e * 2] + bias,
                                              acc[mf][nf][e * 2 + 1] + bias);
                }
            }
        __syncthreads();
#pragma unroll
        for (int t = tid; t < 128 * 8; t += 256) {        // 128 rows x 8 uint4
            const int row = t >> 3, q = (t & 7) * 8;
            *(uint4*)(g_fj + (size_t)row * NN + n0 + q) = *(uint4*)(smb + row * FJS + q);
        }
    }
}

// ---------------- k2: Tpart[s] = fj @ xb^T per chunk. grid (8, SPL) ----------------
#define TPS 68    // k2 staging stride (floats)
__global__ __launch_bounds__(256) void k2() {
    extern __shared__ __align__(16) char sm[];
    const int c0 = blockIdx.x * 64, sp = blockIdx.y;
    const size_t koff = (size_t)sp * KSP;
    float acc[4][2][4] = {};
    gemm_pipe(g_fj + koff, NN, g_xb + (size_t)c0 * NN + koff, NN, KSP, acc, sm);

    const int tid = threadIdx.x, lane = tid & 31, wid = tid >> 5;
    const int mBase = (wid >> 2) * 64, nBase = (wid & 3) * 16;
    const int r = lane >> 2, cc = (lane & 3) * 2;

    // stage [128 h][64 c] fp32, then coalesced float4 row writes
    float* smf = (float*)sm;
#pragma unroll
    for (int mf = 0; mf < 4; mf++)
#pragma unroll
        for (int e = 0; e < 2; e++) {
            const int h = mBase + mf * 16 + r + e * 8;
#pragma unroll
            for (int nf = 0; nf < 2; nf++) {
                const int cl = nBase + nf * 8 + cc;
                *(float2*)(smf + h * TPS + cl) =
                    make_float2(acc[mf][nf][e * 2], acc[mf][nf][e * 2 + 1]);
            }
        }
    __syncthreads();
    float* dst = g_Tpart + (size_t)sp * HS * CC;
#pragma unroll
    for (int t = tid; t < 128 * 16; t += 256) {           // 128 rows x 16 float4
        const int row = t >> 4, q = (t & 15) * 4;
        *(float4*)(dst + (size_t)row * CC + c0 + q) = *(float4*)(smf + row * TPS + q);
    }
}

// ---------------- reduce: Tt[c][h] = bf16(sum_s Tpart), float4 ----------------
__global__ void kred() {
    int i4 = blockIdx.x * 256 + threadIdx.x;
    if (i4 < HS * CC / 4) {
        float4 s = make_float4(0.f, 0.f, 0.f, 0.f);
        const float4* src = (const float4*)g_Tpart;
        for (int p = 0; p < SPL; p++) {
            float4 v = src[(size_t)p * (HS * CC / 4) + i4];
            s.x += v.x; s.y += v.y; s.z += v.z; s.w += v.w;
        }
        int i = i4 * 4;
        int h = i >> 9, c = i & 511;
        g_Tt[(size_t)(c + 0) * HS + h] = __float2bfloat16(s.x);
        g_Tt[(size_t)(c + 1) * HS + h] = __float2bfloat16(s.y);
        g_Tt[(size_t)(c + 2) * HS + h] = __float2bfloat16(s.z);
        g_Tt[(size_t)(c + 3) * HS + h] = __float2bfloat16(s.w);
    }
}

// ---------------- k4: out = x + scale * (fiT @ Tt^T)^T. grid (81, 8) ----------------
#define EPS 132
__global__ __launch_bounds__(256) void k4(const float* __restrict__ x,
                                          const float* __restrict__ agg,
                                          float* __restrict__ out) {
    extern __shared__ __align__(16) char sm[];
    const int n0 = blockIdx.x * 128, c0 = blockIdx.y * 64;
    float acc[4][2][4] = {};
    gemm_pipe(g_fiT + (size_t)n0 * HS, HS, g_Tt + (size_t)c0 * HS, HS, HS, acc, sm);

    const int tid = threadIdx.x, lane = tid & 31, wid = tid >> 5;
    const int mBase = (wid >> 2) * 64, nBase = (wid & 3) * 16;
    const int r = lane >> 2, cc = (lane & 3) * 2;

    float* smf = (float*)sm;
#pragma unroll
    for (int mf = 0; mf < 4; mf++)
#pragma unroll
        for (int e = 0; e < 2; e++) {
            const int nl = mBase + mf * 16 + r + e * 8;
#pragma unroll
            for (int nf = 0; nf < 2; nf++) {
                const int cl = nBase + nf * 8 + cc;
                smf[(cl + 0) * EPS + nl] = acc[mf][nf][e * 2];
                smf[(cl + 1) * EPS + nl] = acc[mf][nf][e * 2 + 1];
            }
        }
    __syncthreads();

    const float scale = agg[0] * (1.0f / (float)NN);
#pragma unroll
    for (int t = tid; t < 2048; t += 256) {
        const int row = t >> 5, col = (t & 31) * 4;
        float4 v = *(float4*)(smf + row * EPS + col);
        const size_t gi = (size_t)(c0 + row) * NN + n0 + col;
        float4 xv = *(const float4*)(x + gi);
        v.x = xv.x + scale * v.x;  v.y = xv.y + scale * v.y;
        v.z = xv.z + scale * v.z;  v.w = xv.w + scale * v.w;
        *(float4*)(out + gi) = v;
    }
}

// ---------------- launch ----------------
extern "C" void kernel_launch(void* const* d_in, const int* in_sizes, int n_in,
                              void* d_out, int out_size) {
    const float* features = (const float*)d_in[0];
    const float* Wi       = (const float*)d_in[1];
    const float* bi       = (const float*)d_in[2];
    const float* Wj       = (const float*)d_in[3];
    const float* bj       = (const float*)d_in[4];
    const float* agg      = (const float*)d_in[5];
    float* out = (float*)d_out;

    cudaFuncSetAttribute(k1, cudaFuncAttributeMaxDynamicSharedMemorySize, SMEM_TOT);
    cudaFuncSetAttribute(k2, cudaFuncAttributeMaxDynamicSharedMemorySize, SMEM_TOT);
    cudaFuncSetAttribute(k4, cudaFuncAttributeMaxDynamicSharedMemorySize, SMEM_TOT);

    k0_w<<<512, 256>>>(Wi, Wj);
    k_pre<<<dim3(NN / 32, CC / 32), dim3(32, 8)>>>(features);
    k1<<<dim3(162, 2), 256, SMEM_TOT>>>(bi, bj);
    k2<<<dim3(8, SPL), 256, SMEM_TOT>>>();
    kred<<<64, 256>>>();
    k4<<<dim3(81, 8), 256, SMEM_TOT>>>(features, agg, out);
}